// round 3
// baseline (speedup 1.0000x reference)
#include <cuda_runtime.h>
#include <cuda_bf16.h>
#include <cstddef>

// Problem constants
#define BB   8
#define TT   4096
#define DD   512
#define UU   512
#define MM   (BB * TT)        // 32768
#define NN   (3 * UU)         // 1536
#define KK   (2 * DD)         // 1024

// GEMM tiling
#define BM 128
#define BN 128
#define BK 16

// Scratch: activated gates [M, 3U] = 201 MB (static device allocation, allowed)
__device__ float g_gates[(size_t)MM * NN];

__global__ __launch_bounds__(256, 2)
void gemm_gates_kernel(const float* __restrict__ x,
                       const float* __restrict__ w,
                       const float* __restrict__ bias)
{
    __shared__ float As[BK][BM + 5];   // pad to 133 floats/row: conflict-light
    __shared__ float Bs[BK][BN];

    const int tid = threadIdx.x;
    const int bx  = blockIdx.x;        // 0..11  (N tiles)
    const int by  = blockIdx.y;        // 0..255 (M tiles)
    const int m0  = by * BM;
    const int n0  = bx * BN;

    const int tx = tid & 15;           // 0..15 -> 8 N-cols each
    const int ty = tid >> 4;           // 0..15 -> 8 M-rows each

    const int a_col  = tid & 15;       // k within tile
    const int a_row0 = tid >> 4;       // row base, + r*16

    float acc[8][8];
    #pragma unroll
    for (int i = 0; i < 8; i++)
        #pragma unroll
        for (int j = 0; j < 8; j++) acc[i][j] = 0.f;

    for (int kk = 0; kk < KK; kk += BK) {
        const bool lowK = (kk < DD);   // whole tile on one side of the window split
        // ---- load A tile (128 x 16), transposed into As[k][m] ----
        #pragma unroll
        for (int r = 0; r < 8; r++) {
            const int row = a_row0 + (r << 4);     // 0..127
            const int m   = m0 + row;
            float v;
            if (lowK) {
                // x[m-1, kk+a_col]; zero at t==0 (batch boundary)
                v = ((m & (TT - 1)) == 0) ? 0.f
                    : x[(size_t)(m - 1) * DD + kk + a_col];
            } else {
                v = x[(size_t)m * DD + (kk - DD) + a_col];
            }
            As[a_col][row] = v;
        }
        // ---- load B tile (16 x 128), float4 ----
        #pragma unroll
        for (int i = 0; i < 2; i++) {
            const int lin  = tid + (i << 8);
            const int krow = lin >> 5;
            const int nc   = (lin & 31) << 2;
            const float4 bv = *(const float4*)&w[(size_t)(kk + krow) * NN + n0 + nc];
            *(float4*)&Bs[krow][nc] = bv;
        }
        __syncthreads();

        #pragma unroll
        for (int k = 0; k < BK; k++) {
            float a[8], b[8];
            #pragma unroll
            for (int i = 0; i < 8; i++) a[i] = As[k][ty * 8 + i];
            const float4 b0 = *(const float4*)&Bs[k][tx * 8];
            const float4 b1 = *(const float4*)&Bs[k][tx * 8 + 4];
            b[0] = b0.x; b[1] = b0.y; b[2] = b0.z; b[3] = b0.w;
            b[4] = b1.x; b[5] = b1.y; b[6] = b1.z; b[7] = b1.w;
            #pragma unroll
            for (int i = 0; i < 8; i++)
                #pragma unroll
                for (int j = 0; j < 8; j++)
                    acc[i][j] = fmaf(a[i], b[j], acc[i][j]);
        }
        __syncthreads();
    }

    // ---- fused activation epilogue ----
    // bx 0..3 -> z (tanh), 4..7 -> f (sigmoid), 8..11 -> o (sigmoid)
    const bool isZ = (bx < 4);
    #pragma unroll
    for (int i = 0; i < 8; i++) {
        const int m = m0 + ty * 8 + i;
        float* gp = &g_gates[(size_t)m * NN + n0 + tx * 8];
        #pragma unroll
        for (int j4 = 0; j4 < 2; j4++) {
            float4 v;
            float vv[4];
            #pragma unroll
            for (int j = 0; j < 4; j++) {
                float g = acc[i][j4 * 4 + j] + bias[n0 + tx * 8 + j4 * 4 + j];
                if (isZ) g = tanhf(g);
                else     g = 1.f / (1.f + __expf(-g));
                vv[j] = g;
            }
            v.x = vv[0]; v.y = vv[1]; v.z = vv[2]; v.w = vv[3];
            *(float4*)&gp[j4 * 4] = v;
        }
    }
}

// fo-pool: c_t = f*c + (1-f)*z = fma(f, c - z, z);  y = o * c
// 32 blocks x 128 threads: one thread per (b,u) channel, unroll-8 prefetch.
__global__ __launch_bounds__(128, 1)
void fopool_kernel(float* __restrict__ out)
{
    const int b = blockIdx.x >> 2;
    const int u = ((blockIdx.x & 3) << 7) + threadIdx.x;
    const float* g = g_gates + (size_t)b * TT * NN;
    float*       y = out     + (size_t)b * TT * UU;

    float c = 0.f;
    for (int t0 = 0; t0 < TT; t0 += 8) {
        float zz[8], ff[8], oo[8];
        #pragma unroll
        for (int i = 0; i < 8; i++) {
            const float* p = g + (size_t)(t0 + i) * NN + u;
            zz[i] = p[0];
            ff[i] = p[UU];
            oo[i] = p[2 * UU];
        }
        #pragma unroll
        for (int i = 0; i < 8; i++) {
            c = fmaf(ff[i], c - zz[i], zz[i]);
            y[(size_t)(t0 + i) * UU + u] = oo[i] * c;
        }
    }
}

extern "C" void kernel_launch(void* const* d_in, const int* in_sizes, int n_in,
                              void* d_out, int out_size)
{
    const float* x    = (const float*)d_in[0];   // [8,4096,512]
    const float* w    = (const float*)d_in[1];   // [2,512,1536]
    const float* bias = (const float*)d_in[2];   // [1536]
    float* out = (float*)d_out;                  // [8,4096,512]

    dim3 ggrid(NN / BN, MM / BM);                // (12, 256)
    gemm_gates_kernel<<<ggrid, 256>>>(x, w, bias);

    fopool_kernel<<<32, 128>>>(out);
}

// round 10
// speedup vs baseline: 2.0833x; 2.0833x over previous
#include <cuda_runtime.h>
#include <cuda_bf16.h>
#include <cstdint>
#include <cstddef>

// ---------------- problem constants ----------------
#define BB 8
#define TT 4096
#define DD 512
#define UU 512
#define MM (BB*TT)      // 32768
#define NN (3*UU)       // 1536
#define KK (2*DD)       // 1024

// ---------------- GEMM tiling (warp-mma, bf16 HMMA) ----------------
#define BM 128
#define BN 256
// BK = 32 bf16 = 64B per logical row
#define NSTAGE 5
#define NCHUNK 96                    // 6 segments * (512/32)
#define A_BYTES (BM*64)              // 8192
#define B_BYTES (BN*64)              // 16384
#define STAGE_BYTES (A_BYTES + B_BYTES)      // 24576
#define SMEM_TOTAL (NSTAGE*STAGE_BYTES + 256) // + alignment slack

// ---------------- fo-pool segmentation ----------------
#define SEGLEN 64
#define NSEG (TT/SEGLEN)            // 64

// ---------------- device scratch ----------------
__device__ float         g_gates[(size_t)MM*NN];          // activated gates
__device__ __nv_bfloat16 g_xh [(size_t)MM*DD];
__device__ __nv_bfloat16 g_xl [(size_t)MM*DD];
__device__ __nv_bfloat16 g_xhs[(size_t)MM*DD];            // shifted (t-1), zero at t==0
__device__ __nv_bfloat16 g_xls[(size_t)MM*DD];
__device__ __nv_bfloat16 g_wh [(size_t)NN*KK];            // transposed [N,K]
__device__ __nv_bfloat16 g_wl [(size_t)NN*KK];
__device__ float g_P [BB*NSEG*UU];
__device__ float g_q [BB*NSEG*UU];
__device__ float g_cs[BB*NSEG*UU];

// ---------------- PTX helpers ----------------
__device__ __forceinline__ uint32_t smem_u32(const void* p) {
    uint32_t a;
    asm("{ .reg .u64 t; cvta.to.shared.u64 t, %1; cvt.u32.u64 %0, t; }" : "=r"(a) : "l"(p));
    return a;
}
__device__ __forceinline__ void cp16(uint32_t dst, const void* src) {
    asm volatile("cp.async.cg.shared.global [%0], [%1], 16;" :: "r"(dst), "l"(src));
}
#define CP_COMMIT() asm volatile("cp.async.commit_group;" ::: "memory")
#define CP_WAIT3()  asm volatile("cp.async.wait_group 3;"  ::: "memory")

__device__ __forceinline__ void ldsm4(uint32_t* r, uint32_t addr) {
    asm volatile("ldmatrix.sync.aligned.m8n8.x4.shared.b16 {%0,%1,%2,%3}, [%4];"
        : "=r"(r[0]), "=r"(r[1]), "=r"(r[2]), "=r"(r[3]) : "r"(addr));
}
__device__ __forceinline__ void mma16816(float* d, const uint32_t* a, const uint32_t* b) {
    asm volatile("mma.sync.aligned.m16n8k16.row.col.f32.bf16.bf16.f32 "
        "{%0,%1,%2,%3}, {%4,%5,%6,%7}, {%8,%9}, {%0,%1,%2,%3};"
        : "+f"(d[0]), "+f"(d[1]), "+f"(d[2]), "+f"(d[3])
        : "r"(a[0]), "r"(a[1]), "r"(a[2]), "r"(a[3]), "r"(b[0]), "r"(b[1]));
}

// 64B logical rows packed 2-per-128B physical row, XOR swizzle on 16B chunks.
// row: logical row index, c: 16B chunk within 64B row (0..3)
__device__ __forceinline__ uint32_t sw_off(int row, int c) {
    int p  = row >> 1;
    int ch = ((row & 1) << 2) | c;
    return (uint32_t)((p << 7) + ((ch ^ (p & 7)) << 4));
}

// ---------------- prep: split x into bf16 hi/lo (+ t-1 shifted copies) --------
__global__ __launch_bounds__(256)
void split_x_kernel(const float* __restrict__ x)
{
    size_t i = (size_t)blockIdx.x * 256 + threadIdx.x;   // float4 index, MM*DD/4
    float4 v = ((const float4*)x)[i];
    __nv_bfloat16 h0 = __float2bfloat16_rn(v.x);
    __nv_bfloat16 h1 = __float2bfloat16_rn(v.y);
    __nv_bfloat16 h2 = __float2bfloat16_rn(v.z);
    __nv_bfloat16 h3 = __float2bfloat16_rn(v.w);
    __nv_bfloat16 l0 = __float2bfloat16_rn(v.x - __bfloat162float(h0));
    __nv_bfloat16 l1 = __float2bfloat16_rn(v.y - __bfloat162float(h1));
    __nv_bfloat16 l2 = __float2bfloat16_rn(v.z - __bfloat162float(h2));
    __nv_bfloat16 l3 = __float2bfloat16_rn(v.w - __bfloat162float(h3));
    ushort4 hv, lv;
    hv.x = __bfloat16_as_ushort(h0); hv.y = __bfloat16_as_ushort(h1);
    hv.z = __bfloat16_as_ushort(h2); hv.w = __bfloat16_as_ushort(h3);
    lv.x = __bfloat16_as_ushort(l0); lv.y = __bfloat16_as_ushort(l1);
    lv.z = __bfloat16_as_ushort(l2); lv.w = __bfloat16_as_ushort(l3);
    ((ushort4*)g_xh)[i] = hv;
    ((ushort4*)g_xl)[i] = lv;
    size_t m = i >> 7;                       // DD/4 = 128 float4 per row
    if (((m + 1) & (TT - 1)) != 0 && (m + 1) < MM) {
        ((ushort4*)g_xhs)[i + 128] = hv;
        ((ushort4*)g_xls)[i + 128] = lv;
    }
    if ((m & (TT - 1)) == 0) {
        ushort4 z = {0, 0, 0, 0};
        ((ushort4*)g_xhs)[i] = z;
        ((ushort4*)g_xls)[i] = z;
    }
}

// ---------------- prep: split + transpose w -> [N, K] bf16 hi/lo --------------
__global__ __launch_bounds__(256)
void split_w_kernel(const float* __restrict__ w)
{
    int id = blockIdx.x * 256 + threadIdx.x;    // < NN*KK
    int k = id & (KK - 1);
    int n = id >> 10;
    float v = w[(size_t)k * NN + n];
    __nv_bfloat16 h = __float2bfloat16_rn(v);
    __nv_bfloat16 l = __float2bfloat16_rn(v - __bfloat162float(h));
    g_wh[(size_t)n * KK + k] = h;
    g_wl[(size_t)n * KK + k] = l;
}

// ---------------- warp-mma GEMM + fused activation epilogue ------------------
// gates[M,1536] = sum of 6 bf16 K-segments of 512:
//  0: xhs*W0h  1: xh*W1h  2: xls*W0h  3: xl*W1h  4: xhs*W0l  5: xh*W1l
__global__ __launch_bounds__(256, 1)
void gemm_mma_kernel(const float* __restrict__ bias)
{
    extern __shared__ char smem_raw[];
    const uint32_t base = (smem_u32(smem_raw) + 127u) & ~127u;
    const int tid = threadIdx.x;
    const int lane = tid & 31;
    const int wid = tid >> 5;
    const int warp_m = wid & 3;          // 4 -> 32 rows each
    const int warp_n = wid >> 2;         // 2 -> 128 cols each
    const int m0 = blockIdx.y * BM;
    const int n0 = blockIdx.x * BN;

    float acc[2][16][4];
    #pragma unroll
    for (int f = 0; f < 2; f++)
        #pragma unroll
        for (int p = 0; p < 16; p++)
            #pragma unroll
            for (int j = 0; j < 4; j++) acc[f][p][j] = 0.f;

    // ---- chunk loader: chunk cc -> stage base sbase ----
    auto load_chunk = [&](int cc, uint32_t sbase) {
        const int seg = cc >> 4, kc = cc & 15;
        const __nv_bfloat16* Aa =
            (seg == 0 || seg == 4) ? g_xhs :
            (seg == 1 || seg == 5) ? g_xh  :
            (seg == 2)             ? g_xls : g_xl;
        const __nv_bfloat16* Ba = (seg < 4) ? g_wh : g_wl;
        const int ako = kc << 5;
        const int bko = ((seg & 1) << 9) + ako;
        const uint32_t ab = sbase, bb = sbase + A_BYTES;
        #pragma unroll
        for (int j = 0; j < 2; j++) {            // A: 128 rows x 64B
            int lin = tid + (j << 8);
            int row = lin >> 2, c = lin & 3;
            cp16(ab + sw_off(row, c),
                 Aa + (size_t)(m0 + row) * DD + ako + (c << 3));
        }
        #pragma unroll
        for (int j = 0; j < 4; j++) {            // B: 256 rows x 64B
            int lin = tid + (j << 8);
            int row = lin >> 2, c = lin & 3;
            cp16(bb + sw_off(row, c),
                 Ba + (size_t)(n0 + row) * KK + bko + (c << 3));
        }
    };

    // prologue: fill NSTAGE-1 stages
    #pragma unroll
    for (int p = 0; p < NSTAGE - 1; p++) {
        load_chunk(p, base + (uint32_t)p * STAGE_BYTES);
        CP_COMMIT();
    }

    // precompute per-lane ldmatrix address components
    const int a_row = warp_m * 32 + (lane & 15);            // + f*16
    const int a_ch  = (lane >> 4);                          // + ks*2
    const int b_row = warp_n * 128 + (lane & 7) + ((lane >> 4) << 3);  // + p*16
    const int b_ch  = ((lane >> 3) & 1);                    // + ks*2

    for (int c = 0; c < NCHUNK; c++) {
        const int s = c % NSTAGE;
        CP_WAIT3();                    // chunk c landed (this thread's groups)
        __syncthreads();               // everyone's chunk c landed; stage s-? reads done
        if (c + NSTAGE - 1 < NCHUNK)
            load_chunk(c + NSTAGE - 1,
                       base + (uint32_t)((c + NSTAGE - 1) % NSTAGE) * STAGE_BYTES);
        CP_COMMIT();                   // always commit (empty group in tail)

        const uint32_t ab = base + (uint32_t)s * STAGE_BYTES;
        const uint32_t bb = ab + A_BYTES;
        #pragma unroll
        for (int ks = 0; ks < 2; ks++) {
            uint32_t af[2][4];
            #pragma unroll
            for (int f = 0; f < 2; f++)
                ldsm4(af[f], ab + sw_off(a_row + f * 16, ks * 2 + a_ch));
            #pragma unroll
            for (int p = 0; p < 8; p++) {
                uint32_t bt[4];
                ldsm4(bt, bb + sw_off(b_row + p * 16, ks * 2 + b_ch));
                mma16816(acc[0][2*p],   af[0], bt);
                mma16816(acc[0][2*p+1], af[0], bt + 2);
                mma16816(acc[1][2*p],   af[1], bt);
                mma16816(acc[1][2*p+1], af[1], bt + 2);
            }
        }
    }

    // ---- fused epilogue: bias + activation -> g_gates ----
    const int ncol0 = n0 + warp_n * 128;
    const int gate  = ncol0 >> 9;       // 0:z(tanh) 1:f 2:o (sigmoid)
    #pragma unroll
    for (int f = 0; f < 2; f++) {
        #pragma unroll
        for (int p = 0; p < 16; p++) {
            const int col = ncol0 + p * 8 + (lane & 3) * 2;
            const float b0 = __ldg(&bias[col]);
            const float b1 = __ldg(&bias[col + 1]);
            #pragma unroll
            for (int h = 0; h < 2; h++) {
                const int row = m0 + warp_m * 32 + f * 16 + (lane >> 2) + h * 8;
                float g0 = acc[f][p][h * 2 + 0] + b0;
                float g1 = acc[f][p][h * 2 + 1] + b1;
                float a0, a1;
                if (gate == 0) {
                    a0 = 2.f / (1.f + __expf(-2.f * g0)) - 1.f;
                    a1 = 2.f / (1.f + __expf(-2.f * g1)) - 1.f;
                } else {
                    a0 = 1.f / (1.f + __expf(-g0));
                    a1 = 1.f / (1.f + __expf(-g1));
                }
                *(float2*)&g_gates[(size_t)row * NN + col] = make_float2(a0, a1);
            }
        }
    }
}

// ---------------- fo-pool: segmented scan ------------------------------------
// c_t = f*c + (1-f)*z  ->  over a segment: c_end = (prod f) * c_start + q
__global__ __launch_bounds__(256)
void fopool_p1()
{
    int g = blockIdx.x * 256 + threadIdx.x;
    int u = g & (UU - 1);
    int seg = (g >> 9) & (NSEG - 1);
    int b = g >> 15;
    const float* gp = g_gates + (size_t)(b * TT + seg * SEGLEN) * NN + u;
    float c = 0.f, P = 1.f;
    #pragma unroll 8
    for (int i = 0; i < SEGLEN; i++) {
        float z = gp[0], f = gp[UU];
        gp += NN;
        c = fmaf(f, c - z, z);
        P *= f;
    }
    size_t o = (size_t)(b * NSEG + seg) * UU + u;
    g_P[o] = P;
    g_q[o] = c;
}

__global__ __launch_bounds__(256)
void fopool_p2()
{
    int id = blockIdx.x * 256 + threadIdx.x;    // < BB*UU
    int u = id & (UU - 1), b = id >> 9;
    float c = 0.f;
    for (int s = 0; s < NSEG; s++) {
        size_t o = (size_t)(b * NSEG + s) * UU + u;
        g_cs[o] = c;
        c = fmaf(g_P[o], c, g_q[o]);
    }
}

__global__ __launch_bounds__(256)
void fopool_p3(float* __restrict__ y)
{
    int g = blockIdx.x * 256 + threadIdx.x;
    int u = g & (UU - 1);
    int seg = (g >> 9) & (NSEG - 1);
    int b = g >> 15;
    float c = g_cs[(size_t)(b * NSEG + seg) * UU + u];
    const float* gp = g_gates + (size_t)(b * TT + seg * SEGLEN) * NN + u;
    float* yp = y + (size_t)(b * TT + seg * SEGLEN) * UU + u;
    #pragma unroll 8
    for (int i = 0; i < SEGLEN; i++) {
        float z = gp[0], f = gp[UU], o_ = gp[2 * UU];
        gp += NN;
        c = fmaf(f, c - z, z);
        *yp = o_ * c;
        yp += UU;
    }
}

// ---------------- launch -----------------------------------------------------
extern "C" void kernel_launch(void* const* d_in, const int* in_sizes, int n_in,
                              void* d_out, int out_size)
{
    const float* x    = (const float*)d_in[0];   // [8,4096,512]
    const float* w    = (const float*)d_in[1];   // [2,512,1536]
    const float* bias = (const float*)d_in[2];   // [1536]
    float* out = (float*)d_out;                  // [8,4096,512]

    cudaFuncSetAttribute(gemm_mma_kernel,
                         cudaFuncAttributeMaxDynamicSharedMemorySize, SMEM_TOTAL);

    split_x_kernel<<<(MM * DD / 4) / 256, 256>>>(x);
    split_w_kernel<<<(NN * KK) / 256, 256>>>(w);

    dim3 gg(NN / BN, MM / BM);                   // (6, 256)
    gemm_mma_kernel<<<gg, 256, SMEM_TOTAL>>>(bias);

    fopool_p1<<<(BB * NSEG * UU) / 256, 256>>>();
    fopool_p2<<<(BB * UU) / 256, 256>>>();
    fopool_p3<<<(BB * NSEG * UU) / 256, 256>>>(out);
}

// round 13
// speedup vs baseline: 4.5315x; 2.1752x over previous
#include <cuda_runtime.h>
#include <cuda_fp16.h>
#include <cstdint>
#include <cstddef>

// ---------------- problem constants ----------------
#define BB 8
#define TT 4096
#define DD 512
#define UU 512
#define MM (BB*TT)      // 32768
#define NN (3*UU)       // 1536
#define KK (2*DD)       // 1024

// ---------------- GEMM tiling (warp-mma, fp16 HMMA, single pass) -------------
#define BM 128
#define BN 256
// BK = 32 fp16 = 64B per logical row
#define NSTAGE 5
#define NCHUNK 32                    // 2 segments * (512/32)
#define A_BYTES (BM*64)              // 8192
#define B_BYTES (BN*64)              // 16384
#define STAGE_BYTES (A_BYTES + B_BYTES)      // 24576
#define SMEM_TOTAL (NSTAGE*STAGE_BYTES + 256)

// ---------------- fo-pool segmentation ----------------
#define SEGLEN 64
#define NSEG (TT/SEGLEN)            // 64

// ---------------- device scratch ----------------
__device__ float  g_gates[(size_t)MM*NN];     // activated gates
__device__ __half g_xh [(size_t)MM*DD];       // x  (fp16)
__device__ __half g_xhs[(size_t)MM*DD];       // x shifted (t-1), zero at t==0
__device__ __half g_wh [(size_t)NN*KK];       // w transposed [N,K] fp16
__device__ float g_P [BB*NSEG*UU];
__device__ float g_q [BB*NSEG*UU];
__device__ float g_cs[BB*NSEG*UU];

// ---------------- PTX helpers ----------------
__device__ __forceinline__ uint32_t smem_u32(const void* p) {
    uint32_t a;
    asm("{ .reg .u64 t; cvta.to.shared.u64 t, %1; cvt.u32.u64 %0, t; }" : "=r"(a) : "l"(p));
    return a;
}
__device__ __forceinline__ void cp16(uint32_t dst, const void* src) {
    asm volatile("cp.async.cg.shared.global [%0], [%1], 16;" :: "r"(dst), "l"(src));
}
#define CP_COMMIT() asm volatile("cp.async.commit_group;" ::: "memory")
#define CP_WAIT3()  asm volatile("cp.async.wait_group 3;"  ::: "memory")

__device__ __forceinline__ void ldsm4(uint32_t* r, uint32_t addr) {
    asm volatile("ldmatrix.sync.aligned.m8n8.x4.shared.b16 {%0,%1,%2,%3}, [%4];"
        : "=r"(r[0]), "=r"(r[1]), "=r"(r[2]), "=r"(r[3]) : "r"(addr));
}
__device__ __forceinline__ void mma16816(float* d, const uint32_t* a, const uint32_t* b) {
    asm volatile("mma.sync.aligned.m16n8k16.row.col.f32.f16.f16.f32 "
        "{%0,%1,%2,%3}, {%4,%5,%6,%7}, {%8,%9}, {%0,%1,%2,%3};"
        : "+f"(d[0]), "+f"(d[1]), "+f"(d[2]), "+f"(d[3])
        : "r"(a[0]), "r"(a[1]), "r"(a[2]), "r"(a[3]), "r"(b[0]), "r"(b[1]));
}

// 64B logical rows packed 2-per-128B physical row, XOR swizzle on 16B chunks.
__device__ __forceinline__ uint32_t sw_off(int row, int c) {
    int p  = row >> 1;
    int ch = ((row & 1) << 2) | c;
    return (uint32_t)((p << 7) + ((ch ^ (p & 7)) << 4));
}

// ---------------- prep: x -> fp16 (+ t-1 shifted copy) -----------------------
__global__ __launch_bounds__(256)
void split_x_kernel(const float* __restrict__ x)
{
    size_t i = (size_t)blockIdx.x * 256 + threadIdx.x;   // float4 index, MM*DD/4
    float4 v = ((const float4*)x)[i];
    ushort4 hv;
    hv.x = __half_as_ushort(__float2half_rn(v.x));
    hv.y = __half_as_ushort(__float2half_rn(v.y));
    hv.z = __half_as_ushort(__float2half_rn(v.z));
    hv.w = __half_as_ushort(__float2half_rn(v.w));
    ((ushort4*)g_xh)[i] = hv;
    size_t m = i >> 7;                       // DD/4 = 128 float4 per row
    if (((m + 1) & (TT - 1)) != 0 && (m + 1) < MM)
        ((ushort4*)g_xhs)[i + 128] = hv;
    if ((m & (TT - 1)) == 0) {
        ushort4 z = {0, 0, 0, 0};
        ((ushort4*)g_xhs)[i] = z;
    }
}

// ---------------- prep: transpose w -> [N, K] fp16 ---------------------------
__global__ __launch_bounds__(256)
void split_w_kernel(const float* __restrict__ w)
{
    int id = blockIdx.x * 256 + threadIdx.x;    // < NN*KK
    int k = id & (KK - 1);
    int n = id >> 10;
    g_wh[(size_t)n * KK + k] = __float2half_rn(w[(size_t)k * NN + n]);
}

// ---------------- warp-mma GEMM + fused activation epilogue ------------------
// gates[M,1536] = xhs * W[0]  +  xh * W[1]      (K = 2*512, fp16, fp32 accum)
__global__ __launch_bounds__(256, 1)
void gemm_mma_kernel(const float* __restrict__ bias)
{
    extern __shared__ char smem_raw[];
    const uint32_t base = (smem_u32(smem_raw) + 127u) & ~127u;
    const int tid = threadIdx.x;
    const int lane = tid & 31;
    const int wid = tid >> 5;
    const int warp_m = wid & 3;          // 4 -> 32 rows each
    const int warp_n = wid >> 2;         // 2 -> 128 cols each
    const int m0 = blockIdx.y * BM;
    const int n0 = blockIdx.x * BN;

    float acc[2][16][4];
    #pragma unroll
    for (int f = 0; f < 2; f++)
        #pragma unroll
        for (int p = 0; p < 16; p++)
            #pragma unroll
            for (int j = 0; j < 4; j++) acc[f][p][j] = 0.f;

    // ---- chunk loader: chunk cc -> stage base sbase ----
    auto load_chunk = [&](int cc, uint32_t sbase) {
        const int seg = cc >> 4, kc = cc & 15;       // seg 0: x_{t-1}, 1: x_t
        const __half* Aa = seg ? g_xh : g_xhs;
        const int ako = kc << 5;
        const int bko = (seg << 9) + ako;
        const uint32_t ab = sbase, bb = sbase + A_BYTES;
        #pragma unroll
        for (int j = 0; j < 2; j++) {            // A: 128 rows x 64B
            int lin = tid + (j << 8);
            int row = lin >> 2, c = lin & 3;
            cp16(ab + sw_off(row, c),
                 Aa + (size_t)(m0 + row) * DD + ako + (c << 3));
        }
        #pragma unroll
        for (int j = 0; j < 4; j++) {            // B: 256 rows x 64B
            int lin = tid + (j << 8);
            int row = lin >> 2, c = lin & 3;
            cp16(bb + sw_off(row, c),
                 g_wh + (size_t)(n0 + row) * KK + bko + (c << 3));
        }
    };

    // prologue: fill NSTAGE-1 stages
    #pragma unroll
    for (int p = 0; p < NSTAGE - 1; p++) {
        load_chunk(p, base + (uint32_t)p * STAGE_BYTES);
        CP_COMMIT();
    }

    // per-lane ldmatrix address components
    const int a_row = warp_m * 32 + (lane & 15);            // + f*16
    const int a_ch  = (lane >> 4);                          // + ks*2
    const int b_row = warp_n * 128 + (lane & 7) + ((lane >> 4) << 3);  // + p*16
    const int b_ch  = ((lane >> 3) & 1);                    // + ks*2

    for (int c = 0; c < NCHUNK; c++) {
        const int s = c % NSTAGE;
        CP_WAIT3();
        __syncthreads();
        if (c + NSTAGE - 1 < NCHUNK)
            load_chunk(c + NSTAGE - 1,
                       base + (uint32_t)((c + NSTAGE - 1) % NSTAGE) * STAGE_BYTES);
        CP_COMMIT();                   // empty group in tail keeps counts aligned

        const uint32_t ab = base + (uint32_t)s * STAGE_BYTES;
        const uint32_t bb = ab + A_BYTES;
        #pragma unroll
        for (int ks = 0; ks < 2; ks++) {
            uint32_t af[2][4];
            #pragma unroll
            for (int f = 0; f < 2; f++)
                ldsm4(af[f], ab + sw_off(a_row + f * 16, ks * 2 + a_ch));
            #pragma unroll
            for (int p = 0; p < 8; p++) {
                uint32_t bt[4];
                ldsm4(bt, bb + sw_off(b_row + p * 16, ks * 2 + b_ch));
                mma16816(acc[0][2*p],   af[0], bt);
                mma16816(acc[0][2*p+1], af[0], bt + 2);
                mma16816(acc[1][2*p],   af[1], bt);
                mma16816(acc[1][2*p+1], af[1], bt + 2);
            }
        }
    }

    // ---- fused epilogue: bias + activation -> g_gates ----
    const int ncol0 = n0 + warp_n * 128;
    const int gate  = ncol0 >> 9;       // 0:z(tanh) 1:f 2:o (sigmoid)
    #pragma unroll
    for (int f = 0; f < 2; f++) {
        #pragma unroll
        for (int p = 0; p < 16; p++) {
            const int col = ncol0 + p * 8 + (lane & 3) * 2;
            const float b0 = __ldg(&bias[col]);
            const float b1 = __ldg(&bias[col + 1]);
            #pragma unroll
            for (int h = 0; h < 2; h++) {
                const int row = m0 + warp_m * 32 + f * 16 + (lane >> 2) + h * 8;
                float g0 = acc[f][p][h * 2 + 0] + b0;
                float g1 = acc[f][p][h * 2 + 1] + b1;
                float a0, a1;
                if (gate == 0) {
                    a0 = 2.f / (1.f + __expf(-2.f * g0)) - 1.f;
                    a1 = 2.f / (1.f + __expf(-2.f * g1)) - 1.f;
                } else {
                    a0 = 1.f / (1.f + __expf(-g0));
                    a1 = 1.f / (1.f + __expf(-g1));
                }
                *(float2*)&g_gates[(size_t)row * NN + col] = make_float2(a0, a1);
            }
        }
    }
}

// ---------------- fo-pool: segmented scan ------------------------------------
__global__ __launch_bounds__(256)
void fopool_p1()
{
    int g = blockIdx.x * 256 + threadIdx.x;
    int u = g & (UU - 1);
    int seg = (g >> 9) & (NSEG - 1);
    int b = g >> 15;
    const float* gp = g_gates + (size_t)(b * TT + seg * SEGLEN) * NN + u;
    float c = 0.f, P = 1.f;
    #pragma unroll 8
    for (int i = 0; i < SEGLEN; i++) {
        float z = gp[0], f = gp[UU];
        gp += NN;
        c = fmaf(f, c - z, z);
        P *= f;
    }
    size_t o = (size_t)(b * NSEG + seg) * UU + u;
    g_P[o] = P;
    g_q[o] = c;
}

__global__ __launch_bounds__(256)
void fopool_p2()
{
    int id = blockIdx.x * 256 + threadIdx.x;    // < BB*UU
    int u = id & (UU - 1), b = id >> 9;
    float c = 0.f;
    for (int s = 0; s < NSEG; s++) {
        size_t o = (size_t)(b * NSEG + s) * UU + u;
        g_cs[o] = c;
        c = fmaf(g_P[o], c, g_q[o]);
    }
}

__global__ __launch_bounds__(256)
void fopool_p3(float* __restrict__ y)
{
    int g = blockIdx.x * 256 + threadIdx.x;
    int u = g & (UU - 1);
    int seg = (g >> 9) & (NSEG - 1);
    int b = g >> 15;
    float c = g_cs[(size_t)(b * NSEG + seg) * UU + u];
    const float* gp = g_gates + (size_t)(b * TT + seg * SEGLEN) * NN + u;
    float* yp = y + (size_t)(b * TT + seg * SEGLEN) * UU + u;
    #pragma unroll 8
    for (int i = 0; i < SEGLEN; i++) {
        float z = gp[0], f = gp[UU], o_ = gp[2 * UU];
        gp += NN;
        c = fmaf(f, c - z, z);
        *yp = o_ * c;
        yp += UU;
    }
}

// ---------------- launch -----------------------------------------------------
extern "C" void kernel_launch(void* const* d_in, const int* in_sizes, int n_in,
                              void* d_out, int out_size)
{
    const float* x    = (const float*)d_in[0];   // [8,4096,512]
    const float* w    = (const float*)d_in[1];   // [2,512,1536]
    const float* bias = (const float*)d_in[2];   // [1536]
    float* out = (float*)d_out;                  // [8,4096,512]

    cudaFuncSetAttribute(gemm_mma_kernel,
                         cudaFuncAttributeMaxDynamicSharedMemorySize, SMEM_TOTAL);

    split_x_kernel<<<(MM * DD / 4) / 256, 256>>>(x);
    split_w_kernel<<<(NN * KK) / 256, 256>>>(w);

    dim3 gg(NN / BN, MM / BM);                   // (6, 256)
    gemm_mma_kernel<<<gg, 256, SMEM_TOTAL>>>(bias);

    fopool_p1<<<(BB * NSEG * UU) / 256, 256>>>();
    fopool_p2<<<(BB * UU) / 256, 256>>>();
    fopool_p3<<<(BB * NSEG * UU) / 256, 256>>>(out);
}

// round 16
// speedup vs baseline: 6.4870x; 1.4315x over previous
#include <cuda_runtime.h>
#include <cuda_fp16.h>
#include <cstdint>
#include <cstddef>

// ---------------- problem constants ----------------
#define BB 8
#define TT 4096
#define DD 512
#define UU 512
#define MM (BB*TT)      // 32768
#define NN (3*UU)       // 1536
#define KK (2*DD)       // 1024

// ---------------- GEMM tiling (warp-mma, fp16, occupancy 2) ------------------
#define BM 128
#define BN 128
// BK = 32 fp16 = 64B per logical row
#define NSTAGE 4
#define NCHUNK 32                    // 2 segments * (512/32)
#define A_BYTES (BM*64)              // 8192
#define B_BYTES (BN*64)              // 8192
#define STAGE_BYTES (A_BYTES + B_BYTES)      // 16384
#define SMEM_TOTAL (NSTAGE*STAGE_BYTES + 256)

// ---------------- fo-pool segmentation ----------------
#define SEGLEN 64
#define NSEG (TT/SEGLEN)            // 64

// ---------------- device scratch ----------------
__device__ __half g_gates[(size_t)MM*NN];     // activated gates (fp16)
__device__ __half g_xh[(size_t)MM*DD];        // x (fp16)
__device__ __half g_wh[(size_t)NN*KK];        // w transposed [N,K] fp16
__device__ float g_P [BB*NSEG*UU];
__device__ float g_q [BB*NSEG*UU];
__device__ float g_cs[BB*NSEG*UU];

// ---------------- PTX helpers ----------------
__device__ __forceinline__ uint32_t smem_u32(const void* p) {
    uint32_t a;
    asm("{ .reg .u64 t; cvta.to.shared.u64 t, %1; cvt.u32.u64 %0, t; }" : "=r"(a) : "l"(p));
    return a;
}
__device__ __forceinline__ void cp16(uint32_t dst, const void* src) {
    asm volatile("cp.async.cg.shared.global [%0], [%1], 16;" :: "r"(dst), "l"(src));
}
// zero-fill variant: sz=16 normal, sz=0 -> fills 16B of zeros
__device__ __forceinline__ void cp16z(uint32_t dst, const void* src, uint32_t sz) {
    asm volatile("cp.async.cg.shared.global [%0], [%1], 16, %2;"
                 :: "r"(dst), "l"(src), "r"(sz));
}
#define CP_COMMIT() asm volatile("cp.async.commit_group;" ::: "memory")
#define CP_WAIT2()  asm volatile("cp.async.wait_group 2;"  ::: "memory")

__device__ __forceinline__ void ldsm4(uint32_t* r, uint32_t addr) {
    asm volatile("ldmatrix.sync.aligned.m8n8.x4.shared.b16 {%0,%1,%2,%3}, [%4];"
        : "=r"(r[0]), "=r"(r[1]), "=r"(r[2]), "=r"(r[3]) : "r"(addr));
}
__device__ __forceinline__ void mma16816(float* d, const uint32_t* a, const uint32_t* b) {
    asm volatile("mma.sync.aligned.m16n8k16.row.col.f32.f16.f16.f32 "
        "{%0,%1,%2,%3}, {%4,%5,%6,%7}, {%8,%9}, {%0,%1,%2,%3};"
        : "+f"(d[0]), "+f"(d[1]), "+f"(d[2]), "+f"(d[3])
        : "r"(a[0]), "r"(a[1]), "r"(a[2]), "r"(a[3]), "r"(b[0]), "r"(b[1]));
}

// 64B logical rows packed 2-per-128B physical row, XOR swizzle on 16B chunks.
__device__ __forceinline__ uint32_t sw_off(int row, int c) {
    int p  = row >> 1;
    int ch = ((row & 1) << 2) | c;
    return (uint32_t)((p << 7) + ((ch ^ (p & 7)) << 4));
}

// ---------------- prep: x -> fp16 --------------------------------------------
__global__ __launch_bounds__(256)
void split_x_kernel(const float* __restrict__ x)
{
    size_t i = (size_t)blockIdx.x * 256 + threadIdx.x;   // float4 index, MM*DD/4
    float4 v = ((const float4*)x)[i];
    ushort4 hv;
    hv.x = __half_as_ushort(__float2half_rn(v.x));
    hv.y = __half_as_ushort(__float2half_rn(v.y));
    hv.z = __half_as_ushort(__float2half_rn(v.z));
    hv.w = __half_as_ushort(__float2half_rn(v.w));
    ((ushort4*)g_xh)[i] = hv;
}

// ---------------- prep: transpose w -> [N, K] fp16 ---------------------------
__global__ __launch_bounds__(256)
void split_w_kernel(const float* __restrict__ w)
{
    int id = blockIdx.x * 256 + threadIdx.x;    // < NN*KK
    int k = id & (KK - 1);
    int n = id >> 10;
    g_wh[(size_t)n * KK + k] = __float2half_rn(w[(size_t)k * NN + n]);
}

// ---------------- warp-mma GEMM + fused activation epilogue ------------------
// gates[M,1536] = x_{t-1} * W[0]  +  x_t * W[1]   (K = 2*512, fp16, fp32 accum)
__global__ __launch_bounds__(256, 2)
void gemm_mma_kernel(const float* __restrict__ bias)
{
    extern __shared__ char smem_raw[];
    const uint32_t base = (smem_u32(smem_raw) + 127u) & ~127u;
    const int tid = threadIdx.x;
    const int lane = tid & 31;
    const int wid = tid >> 5;
    const int warp_m = wid & 3;          // 4 -> 32 rows each
    const int warp_n = wid >> 2;         // 2 -> 64 cols each
    const int m0 = blockIdx.y * BM;
    const int n0 = blockIdx.x * BN;

    float acc[2][8][4];
    #pragma unroll
    for (int f = 0; f < 2; f++)
        #pragma unroll
        for (int p = 0; p < 8; p++)
            #pragma unroll
            for (int j = 0; j < 4; j++) acc[f][p][j] = 0.f;

    // ---- chunk loader: chunk cc -> stage base sbase ----
    // seg 0: A row m reads x[m-1] (zero at batch start); seg 1: x[m]
    auto load_chunk = [&](int cc, uint32_t sbase) {
        const int seg = cc >> 4, kc = cc & 15;
        const int ako = kc << 5;
        const int bko = (seg << 9) + ako;
        const uint32_t ab = sbase, bb = sbase + A_BYTES;
        #pragma unroll
        for (int j = 0; j < 2; j++) {            // A: 128 rows x 64B
            int lin = tid + (j << 8);
            int row = lin >> 2, c4 = lin & 3;
            int m = m0 + row - (seg ^ 1);        // seg0 -> m-1
            uint32_t sz = 16;
            if ((seg == 0) & (row == 0) & ((m0 & (TT - 1)) == 0)) { sz = 0; m = m0; }
            cp16z(ab + sw_off(row, c4),
                  g_xh + (size_t)m * DD + ako + (c4 << 3), sz);
        }
        #pragma unroll
        for (int j = 0; j < 2; j++) {            // B: 128 rows x 64B
            int lin = tid + (j << 8);
            int row = lin >> 2, c4 = lin & 3;
            cp16(bb + sw_off(row, c4),
                 g_wh + (size_t)(n0 + row) * KK + bko + (c4 << 3));
        }
    };

    // prologue: fill NSTAGE-1 stages
    #pragma unroll
    for (int p = 0; p < NSTAGE - 1; p++) {
        load_chunk(p, base + (uint32_t)p * STAGE_BYTES);
        CP_COMMIT();
    }

    // per-lane ldmatrix address components
    const int a_row = warp_m * 32 + (lane & 15);                      // + f*16
    const int a_ch  = (lane >> 4);                                    // + ks*2
    const int b_row = warp_n * 64 + (lane & 7) + ((lane >> 4) << 3);  // + p*16
    const int b_ch  = ((lane >> 3) & 1);                              // + ks*2

    for (int c = 0; c < NCHUNK; c++) {
        const int s = c & (NSTAGE - 1);
        CP_WAIT2();
        __syncthreads();
        if (c + NSTAGE - 1 < NCHUNK)
            load_chunk(c + NSTAGE - 1,
                       base + (uint32_t)((c + NSTAGE - 1) & (NSTAGE - 1)) * STAGE_BYTES);
        CP_COMMIT();                   // empty group in tail keeps counts aligned

        const uint32_t ab = base + (uint32_t)s * STAGE_BYTES;
        const uint32_t bb = ab + A_BYTES;
        #pragma unroll
        for (int ks = 0; ks < 2; ks++) {
            uint32_t af[2][4];
            #pragma unroll
            for (int f = 0; f < 2; f++)
                ldsm4(af[f], ab + sw_off(a_row + f * 16, ks * 2 + a_ch));
            #pragma unroll
            for (int p = 0; p < 4; p++) {
                uint32_t bt[4];
                ldsm4(bt, bb + sw_off(b_row + p * 16, ks * 2 + b_ch));
                mma16816(acc[0][2*p],   af[0], bt);
                mma16816(acc[0][2*p+1], af[0], bt + 2);
                mma16816(acc[1][2*p],   af[1], bt);
                mma16816(acc[1][2*p+1], af[1], bt + 2);
            }
        }
    }

    // ---- fused epilogue: bias + activation -> g_gates (fp16) ----
    const int ncol0 = n0 + warp_n * 64;
    const int gate  = ncol0 >> 9;       // 0:z(tanh) 1:f 2:o (sigmoid)
    #pragma unroll
    for (int f = 0; f < 2; f++) {
        #pragma unroll
        for (int p = 0; p < 8; p++) {
            const int col = ncol0 + p * 8 + (lane & 3) * 2;
            const float b0 = __ldg(&bias[col]);
            const float b1 = __ldg(&bias[col + 1]);
            #pragma unroll
            for (int h = 0; h < 2; h++) {
                const int row = m0 + warp_m * 32 + f * 16 + (lane >> 2) + h * 8;
                float g0 = acc[f][p][h * 2 + 0] + b0;
                float g1 = acc[f][p][h * 2 + 1] + b1;
                float a0, a1;
                if (gate == 0) {
                    a0 = 2.f / (1.f + __expf(-2.f * g0)) - 1.f;
                    a1 = 2.f / (1.f + __expf(-2.f * g1)) - 1.f;
                } else {
                    a0 = 1.f / (1.f + __expf(-g0));
                    a1 = 1.f / (1.f + __expf(-g1));
                }
                *(__half2*)&g_gates[(size_t)row * NN + col] =
                    __floats2half2_rn(a0, a1);
            }
        }
    }
}

// ---------------- fo-pool: segmented scan (half2, 2 units/thread) ------------
__global__ __launch_bounds__(256)
void fopool_p1()
{
    int g = blockIdx.x * 256 + threadIdx.x;     // BB*NSEG*256
    int up = g & 255;                           // unit pair
    int seg = (g >> 8) & (NSEG - 1);
    int b = g >> 14;
    const __half* gp = g_gates + (size_t)(b * TT + seg * SEGLEN) * NN + up * 2;
    float cx = 0.f, cy = 0.f, Px = 1.f, Py = 1.f;
    #pragma unroll 8
    for (int i = 0; i < SEGLEN; i++) {
        float2 z = __half22float2(*(const __half2*)gp);
        float2 f = __half22float2(*(const __half2*)(gp + UU));
        gp += NN;
        cx = fmaf(f.x, cx - z.x, z.x);
        cy = fmaf(f.y, cy - z.y, z.y);
        Px *= f.x; Py *= f.y;
    }
    size_t o = (size_t)(b * NSEG + seg) * UU + up * 2;
    g_P[o] = Px; g_P[o + 1] = Py;
    g_q[o] = cx; g_q[o + 1] = cy;
}

__global__ __launch_bounds__(256)
void fopool_p2()
{
    int id = blockIdx.x * 256 + threadIdx.x;    // < BB*UU
    int u = id & (UU - 1), b = id >> 9;
    float c = 0.f;
    for (int s = 0; s < NSEG; s++) {
        size_t o = (size_t)(b * NSEG + s) * UU + u;
        g_cs[o] = c;
        c = fmaf(g_P[o], c, g_q[o]);
    }
}

__global__ __launch_bounds__(256)
void fopool_p3(float* __restrict__ y)
{
    int g = blockIdx.x * 256 + threadIdx.x;
    int up = g & 255;
    int seg = (g >> 8) & (NSEG - 1);
    int b = g >> 14;
    size_t o = (size_t)(b * NSEG + seg) * UU + up * 2;
    float cx = g_cs[o], cy = g_cs[o + 1];
    const __half* gp = g_gates + (size_t)(b * TT + seg * SEGLEN) * NN + up * 2;
    float* yp = y + (size_t)(b * TT + seg * SEGLEN) * UU + up * 2;
    #pragma unroll 8
    for (int i = 0; i < SEGLEN; i++) {
        float2 z  = __half22float2(*(const __half2*)gp);
        float2 f  = __half22float2(*(const __half2*)(gp + UU));
        float2 oo = __half22float2(*(const __half2*)(gp + 2 * UU));
        gp += NN;
        cx = fmaf(f.x, cx - z.x, z.x);
        cy = fmaf(f.y, cy - z.y, z.y);
        *(float2*)yp = make_float2(oo.x * cx, oo.y * cy);
        yp += UU;
    }
}

// ---------------- launch -----------------------------------------------------
extern "C" void kernel_launch(void* const* d_in, const int* in_sizes, int n_in,
                              void* d_out, int out_size)
{
    const float* x    = (const float*)d_in[0];   // [8,4096,512]
    const float* w    = (const float*)d_in[1];   // [2,512,1536]
    const float* bias = (const float*)d_in[2];   // [1536]
    float* out = (float*)d_out;                  // [8,4096,512]

    cudaFuncSetAttribute(gemm_mma_kernel,
                         cudaFuncAttributeMaxDynamicSharedMemorySize, SMEM_TOTAL);

    split_x_kernel<<<(MM * DD / 4) / 256, 256>>>(x);
    split_w_kernel<<<(NN * KK) / 256, 256>>>(w);

    dim3 gg(NN / BN, MM / BM);                   // (12, 256)
    gemm_mma_kernel<<<gg, 256, SMEM_TOTAL>>>(bias);

    fopool_p1<<<BB * NSEG, 256>>>();
    fopool_p2<<<(BB * UU) / 256, 256>>>();
    fopool_p3<<<BB * NSEG, 256>>>(out);
}

// round 17
// speedup vs baseline: 6.9376x; 1.0695x over previous
#include <cuda_runtime.h>
#include <cuda_fp16.h>
#include <cstdint>
#include <cstddef>

// ---------------- problem constants ----------------
#define BB 8
#define TT 4096
#define DD 512
#define UU 512
#define MM (BB*TT)      // 32768
#define NN (3*UU)       // 1536
#define KK (2*DD)       // 1024

// ---------------- GEMM tiling (warp-mma, fp16, occupancy 2) ------------------
#define BM 128
#define BN 128
// BK = 64 fp16 = 128B per smem row
#define NSTAGE 3
#define NCHUNK 16                    // 2 segments * (512/64)
#define A_BYTES (BM*128)             // 16384
#define B_BYTES (BN*128)             // 16384
#define STAGE_BYTES (A_BYTES + B_BYTES)      // 32768
#define SMEM_TOTAL (NSTAGE*STAGE_BYTES + 256)

// ---------------- fo-pool segmentation ----------------
#define SEGLEN 32
#define NSEG (TT/SEGLEN)            // 128

// ---------------- device scratch ----------------
__device__ __half g_gates[(size_t)MM*NN];     // activated gates (fp16)
__device__ __half g_xh[(size_t)MM*DD];        // x (fp16)
__device__ __half g_wh[(size_t)NN*KK];        // w transposed [N,K] fp16
__device__ float g_P [BB*NSEG*UU];
__device__ float g_q [BB*NSEG*UU];
__device__ float g_cs[BB*NSEG*UU];

// ---------------- PTX helpers ----------------
__device__ __forceinline__ uint32_t smem_u32(const void* p) {
    uint32_t a;
    asm("{ .reg .u64 t; cvta.to.shared.u64 t, %1; cvt.u32.u64 %0, t; }" : "=r"(a) : "l"(p));
    return a;
}
__device__ __forceinline__ void cp16(uint32_t dst, const void* src) {
    asm volatile("cp.async.cg.shared.global [%0], [%1], 16;" :: "r"(dst), "l"(src));
}
// zero-fill variant: sz=16 normal, sz=0 -> fills 16B of zeros
__device__ __forceinline__ void cp16z(uint32_t dst, const void* src, uint32_t sz) {
    asm volatile("cp.async.cg.shared.global [%0], [%1], 16, %2;"
                 :: "r"(dst), "l"(src), "r"(sz));
}
#define CP_COMMIT() asm volatile("cp.async.commit_group;" ::: "memory")
#define CP_WAIT1()  asm volatile("cp.async.wait_group 1;"  ::: "memory")

__device__ __forceinline__ void ldsm4(uint32_t* r, uint32_t addr) {
    asm volatile("ldmatrix.sync.aligned.m8n8.x4.shared.b16 {%0,%1,%2,%3}, [%4];"
        : "=r"(r[0]), "=r"(r[1]), "=r"(r[2]), "=r"(r[3]) : "r"(addr));
}
__device__ __forceinline__ void mma16816(float* d, const uint32_t* a, const uint32_t* b) {
    asm volatile("mma.sync.aligned.m16n8k16.row.col.f32.f16.f16.f32 "
        "{%0,%1,%2,%3}, {%4,%5,%6,%7}, {%8,%9}, {%0,%1,%2,%3};"
        : "+f"(d[0]), "+f"(d[1]), "+f"(d[2]), "+f"(d[3])
        : "r"(a[0]), "r"(a[1]), "r"(a[2]), "r"(a[3]), "r"(b[0]), "r"(b[1]));
}

// classic SW128 swizzle: 128B rows, 16B chunks, chunk ^= (row & 7)
__device__ __forceinline__ uint32_t sw128(int row, int c) {
    return (uint32_t)((row << 7) + ((c ^ (row & 7)) << 4));
}

// ---------------- prep: x -> fp16 --------------------------------------------
__global__ __launch_bounds__(256)
void split_x_kernel(const float* __restrict__ x)
{
    size_t i = (size_t)blockIdx.x * 256 + threadIdx.x;   // float4 index, MM*DD/4
    float4 v = ((const float4*)x)[i];
    ushort4 hv;
    hv.x = __half_as_ushort(__float2half_rn(v.x));
    hv.y = __half_as_ushort(__float2half_rn(v.y));
    hv.z = __half_as_ushort(__float2half_rn(v.z));
    hv.w = __half_as_ushort(__float2half_rn(v.w));
    ((ushort4*)g_xh)[i] = hv;
}

// ---------------- prep: transpose w -> [N, K] fp16 ---------------------------
__global__ __launch_bounds__(256)
void split_w_kernel(const float* __restrict__ w)
{
    int id = blockIdx.x * 256 + threadIdx.x;    // < NN*KK
    int k = id & (KK - 1);
    int n = id >> 10;
    g_wh[(size_t)n * KK + k] = __float2half_rn(w[(size_t)k * NN + n]);
}

// ---------------- warp-mma GEMM + fused activation epilogue ------------------
// gates[M,1536] = x_{t-1} * W[0]  +  x_t * W[1]   (K = 2*512, fp16, fp32 accum)
__global__ __launch_bounds__(256, 2)
void gemm_mma_kernel(const float* __restrict__ bias)
{
    extern __shared__ char smem_raw[];
    const uint32_t base = (smem_u32(smem_raw) + 127u) & ~127u;
    const int tid = threadIdx.x;
    const int lane = tid & 31;
    const int wid = tid >> 5;
    const int warp_m = wid & 3;          // 4 -> 32 rows each
    const int warp_n = wid >> 2;         // 2 -> 64 cols each
    const int m0 = blockIdx.y * BM;
    const int n0 = blockIdx.x * BN;

    float acc[2][8][4];
    #pragma unroll
    for (int f = 0; f < 2; f++)
        #pragma unroll
        for (int p = 0; p < 8; p++)
            #pragma unroll
            for (int j = 0; j < 4; j++) acc[f][p][j] = 0.f;

    // ---- chunk loader: chunk cc -> stage base sbase ----
    // seg 0: A row m reads x[m-1] (zero at batch start); seg 1: x[m]
    auto load_chunk = [&](int cc, uint32_t sbase) {
        const int seg = cc >> 3, kc = cc & 7;
        const int ako = kc << 6;             // halves
        const int bko = (seg << 9) + ako;
        const uint32_t ab = sbase, bb = sbase + A_BYTES;
        #pragma unroll
        for (int j = 0; j < 4; j++) {            // A: 128 rows x 128B
            int lin = tid + (j << 8);
            int row = lin >> 3, c8 = lin & 7;
            int m = m0 + row - (seg ^ 1);        // seg0 -> m-1
            uint32_t sz = 16;
            if ((seg == 0) & (row == 0) & ((m0 & (TT - 1)) == 0)) { sz = 0; m = m0; }
            cp16z(ab + sw128(row, c8),
                  g_xh + (size_t)m * DD + ako + (c8 << 3), sz);
        }
        #pragma unroll
        for (int j = 0; j < 4; j++) {            // B: 128 rows x 128B
            int lin = tid + (j << 8);
            int row = lin >> 3, c8 = lin & 7;
            cp16(bb + sw128(row, c8),
                 g_wh + (size_t)(n0 + row) * KK + bko + (c8 << 3));
        }
    };

    // prologue: fill NSTAGE-1 = 2 stages
    load_chunk(0, base);
    CP_COMMIT();
    load_chunk(1, base + STAGE_BYTES);
    CP_COMMIT();

    // per-lane ldmatrix address components
    const int a_row = warp_m * 32 + (lane & 15);                      // + f*16
    const int a_ch  = (lane >> 4);                                    // + ks*2
    const int b_row = warp_n * 64 + (lane & 7) + ((lane >> 4) << 3);  // + p*16
    const int b_ch  = ((lane >> 3) & 1);                              // + ks*2

    int s = 0;                           // stage of chunk c (mod 3)
    for (int c = 0; c < NCHUNK; c++) {
        CP_WAIT1();                      // chunk c's group retired
        __syncthreads();
        if (c + 2 < NCHUNK) {
            int sn = s + 2; if (sn >= NSTAGE) sn -= NSTAGE;
            load_chunk(c + 2, base + (uint32_t)sn * STAGE_BYTES);
        }
        CP_COMMIT();                     // empty group in tail keeps counts aligned

        const uint32_t ab = base + (uint32_t)s * STAGE_BYTES;
        const uint32_t bb = ab + A_BYTES;
        #pragma unroll
        for (int ks = 0; ks < 4; ks++) {
            uint32_t af[2][4];
            #pragma unroll
            for (int f = 0; f < 2; f++)
                ldsm4(af[f], ab + sw128(a_row + f * 16, ks * 2 + a_ch));
            #pragma unroll
            for (int p = 0; p < 4; p++) {
                uint32_t bt[4];
                ldsm4(bt, bb + sw128(b_row + p * 16, ks * 2 + b_ch));
                mma16816(acc[0][2*p],   af[0], bt);
                mma16816(acc[0][2*p+1], af[0], bt + 2);
                mma16816(acc[1][2*p],   af[1], bt);
                mma16816(acc[1][2*p+1], af[1], bt + 2);
            }
        }
        if (++s >= NSTAGE) s -= NSTAGE;
    }

    // ---- fused epilogue: bias + activation -> g_gates (fp16) ----
    const int ncol0 = n0 + warp_n * 64;
    const int gate  = ncol0 >> 9;       // 0:z(tanh) 1:f 2:o (sigmoid)
    #pragma unroll
    for (int f = 0; f < 2; f++) {
        #pragma unroll
        for (int p = 0; p < 8; p++) {
            const int col = ncol0 + p * 8 + (lane & 3) * 2;
            const float b0 = __ldg(&bias[col]);
            const float b1 = __ldg(&bias[col + 1]);
            #pragma unroll
            for (int h = 0; h < 2; h++) {
                const int row = m0 + warp_m * 32 + f * 16 + (lane >> 2) + h * 8;
                float g0 = acc[f][p][h * 2 + 0] + b0;
                float g1 = acc[f][p][h * 2 + 1] + b1;
                float a0, a1;
                if (gate == 0) {
                    a0 = 2.f / (1.f + __expf(-2.f * g0)) - 1.f;
                    a1 = 2.f / (1.f + __expf(-2.f * g1)) - 1.f;
                } else {
                    a0 = 1.f / (1.f + __expf(-g0));
                    a1 = 1.f / (1.f + __expf(-g1));
                }
                *(__half2*)&g_gates[(size_t)row * NN + col] =
                    __floats2half2_rn(a0, a1);
            }
        }
    }
}

// ---------------- fo-pool: segmented scan (half2, 2 units/thread) ------------
__global__ __launch_bounds__(256)
void fopool_p1()
{
    int g = blockIdx.x * 256 + threadIdx.x;     // BB*NSEG*256
    int up = g & 255;                           // unit pair
    int seg = (g >> 8) & (NSEG - 1);
    int b = g >> 15;                            // 256*NSEG = 32768 per batch
    const __half* gp = g_gates + (size_t)(b * TT + seg * SEGLEN) * NN + up * 2;
    float cx = 0.f, cy = 0.f, Px = 1.f, Py = 1.f;
    #pragma unroll 8
    for (int i = 0; i < SEGLEN; i++) {
        float2 z = __half22float2(*(const __half2*)gp);
        float2 f = __half22float2(*(const __half2*)(gp + UU));
        gp += NN;
        cx = fmaf(f.x, cx - z.x, z.x);
        cy = fmaf(f.y, cy - z.y, z.y);
        Px *= f.x; Py *= f.y;
    }
    size_t o = (size_t)(b * NSEG + seg) * UU + up * 2;
    g_P[o] = Px; g_P[o + 1] = Py;
    g_q[o] = cx; g_q[o + 1] = cy;
}

__global__ __launch_bounds__(256)
void fopool_p2()
{
    int id = blockIdx.x * 256 + threadIdx.x;    // < BB*UU
    int u = id & (UU - 1), b = id >> 9;
    float c = 0.f;
    for (int s = 0; s < NSEG; s++) {
        size_t o = (size_t)(b * NSEG + s) * UU + u;
        g_cs[o] = c;
        c = fmaf(g_P[o], c, g_q[o]);
    }
}

__global__ __launch_bounds__(256)
void fopool_p3(float* __restrict__ y)
{
    int g = blockIdx.x * 256 + threadIdx.x;
    int up = g & 255;
    int seg = (g >> 8) & (NSEG - 1);
    int b = g >> 15;
    size_t o = (size_t)(b * NSEG + seg) * UU + up * 2;
    float cx = g_cs[o], cy = g_cs[o + 1];
    const __half* gp = g_gates + (size_t)(b * TT + seg * SEGLEN) * NN + up * 2;
    float* yp = y + (size_t)(b * TT + seg * SEGLEN) * UU + up * 2;
    #pragma unroll 8
    for (int i = 0; i < SEGLEN; i++) {
        float2 z  = __half22float2(*(const __half2*)gp);
        float2 f  = __half22float2(*(const __half2*)(gp + UU));
        float2 oo = __half22float2(*(const __half2*)(gp + 2 * UU));
        gp += NN;
        cx = fmaf(f.x, cx - z.x, z.x);
        cy = fmaf(f.y, cy - z.y, z.y);
        *(float2*)yp = make_float2(oo.x * cx, oo.y * cy);
        yp += UU;
    }
}

// ---------------- launch -----------------------------------------------------
extern "C" void kernel_launch(void* const* d_in, const int* in_sizes, int n_in,
                              void* d_out, int out_size)
{
    const float* x    = (const float*)d_in[0];   // [8,4096,512]
    const float* w    = (const float*)d_in[1];   // [2,512,1536]
    const float* bias = (const float*)d_in[2];   // [1536]
    float* out = (float*)d_out;                  // [8,4096,512]

    cudaFuncSetAttribute(gemm_mma_kernel,
                         cudaFuncAttributeMaxDynamicSharedMemorySize, SMEM_TOTAL);

    split_x_kernel<<<(MM * DD / 4) / 256, 256>>>(x);
    split_w_kernel<<<(NN * KK) / 256, 256>>>(w);

    dim3 gg(NN / BN, MM / BM);                   // (12, 256)
    gemm_mma_kernel<<<gg, 256, SMEM_TOTAL>>>(bias);

    fopool_p1<<<BB * NSEG, 256>>>();
    fopool_p2<<<(BB * UU) / 256, 256>>>();
    fopool_p3<<<BB * NSEG, 256>>>(out);
}